// round 15
// baseline (speedup 1.0000x reference)
#include <cuda_runtime.h>
#include <cuda_fp16.h>
#include <cstdint>

#define N_NODES 50000
#define E_RAW   800000
#define E_TOT   (E_RAW + N_NODES)   // 850000 with self loops
#define MAXH    4
#define MAXHC   256
#define SCAN_B  1024
#define ROW_H0  25088               // pipeline split point (divisible by 128)

// ---------------- device scratch (static, allocation-free) ----------------
__device__ __half g_hh  [(size_t)(N_NODES + 128) * MAXHC]; // fp16 features (+pad rows)
__device__ __half g_xphA[(size_t)N_NODES * MAXHC];         // transformed features (parity A)
__device__ __half g_xphB[(size_t)N_NODES * MAXHC];         // transformed features (parity B)
__device__ __half g_wh  [3 * MAXHC * MAXHC];               // W^T fp16, all 3 layers
__device__ float g_sA [(size_t)N_NODES * MAXH];            // scores parity A
__device__ float g_dA [(size_t)N_NODES * MAXH];
__device__ float g_sB [(size_t)N_NODES * MAXH];            // scores parity B
__device__ float g_dB [(size_t)N_NODES * MAXH];
// CSR by destination
__device__ int g_deg [N_NODES];
__device__ int g_cur [N_NODES];
__device__ int g_off [N_NODES + 1];
__device__ int g_bsum[64];
__device__ int g_srcs[E_TOT];

// ---------------- small PTX helpers ----------------
__device__ __forceinline__ uint32_t smem_u32(const void* p) {
    uint32_t a;
    asm("{ .reg .u64 t; cvta.to.shared.u64 t, %1; cvt.u32.u64 %0, t; }" : "=r"(a) : "l"(p));
    return a;
}
__device__ __forceinline__ void ldm_x4(uint32_t& r0, uint32_t& r1, uint32_t& r2, uint32_t& r3,
                                       uint32_t addr) {
    asm volatile("ldmatrix.sync.aligned.m8n8.x4.shared.b16 {%0,%1,%2,%3}, [%4];"
                 : "=r"(r0), "=r"(r1), "=r"(r2), "=r"(r3) : "r"(addr));
}
__device__ __forceinline__ void mma_f16(float* d, const uint32_t* a, uint32_t b0, uint32_t b1) {
    asm volatile(
        "mma.sync.aligned.m16n8k16.row.col.f32.f16.f16.f32 "
        "{%0,%1,%2,%3}, {%4,%5,%6,%7}, {%8,%9}, {%0,%1,%2,%3};"
        : "+f"(d[0]), "+f"(d[1]), "+f"(d[2]), "+f"(d[3])
        : "r"(a[0]), "r"(a[1]), "r"(a[2]), "r"(a[3]), "r"(b0), "r"(b1));
}
__device__ __forceinline__ void cp_async16(uint32_t dst, const void* src) {
    asm volatile("cp.async.ca.shared.global [%0], [%1], 16;" :: "r"(dst), "l"(src));
}
#define CP_COMMIT()  asm volatile("cp.async.commit_group;")
#define CP_WAIT(n)   asm volatile("cp.async.wait_group %0;" :: "n"(n) : "memory")

// ---------------- all-layer weight transpose + fp16 convert ----------------
__global__ void prep_weights_all(const float* __restrict__ W0, const float* __restrict__ W1,
                                 const float* __restrict__ W2, __half* __restrict__ out) {
    __shared__ float t[32][33];
    int layer = blockIdx.z;
    const float* W; int K, N; __half* dst;
    if (layer == 0)      { W = W0; K = 128; N = 256; dst = out; }
    else if (layer == 1) { W = W1; K = 256; N = 256; dst = out + 65536; }
    else                 { W = W2; K = 256; N = 128; dst = out + 131072; }
    int bn = blockIdx.x * 32, bk = blockIdx.y * 32;
    if (bn >= N || bk >= K) return;
    int x = threadIdx.x, y = threadIdx.y;
    #pragma unroll
    for (int j = 0; j < 32; j += 8) t[y + j][x] = W[(size_t)(bk + y + j) * N + bn + x];
    __syncthreads();
    #pragma unroll
    for (int j = 0; j < 32; j += 8)
        dst[(size_t)(bn + y + j) * K + bk + x] = __float2half_rn(t[x][y + j]);
}

// ---------------- x (fp32) -> fp16 ----------------
__global__ void conv_x_kernel(const float* __restrict__ x, __half* __restrict__ out, int n2) {
    int i = blockIdx.x * blockDim.x + threadIdx.x;
    if (i < n2) {
        float2 v = *(const float2*)&x[i * 2];
        *(__half2*)&out[i * 2] = __floats2half2_rn(v.x, v.y);
    }
}

// ---------------- fp16 tensor GEMM, all-cp.async, 4-stage pipeline ----------------
#define PITCH    40
#define TILE_B   (128 * PITCH * 2)
#define NSTAGE   4
#define GEMM_SMEM (NSTAGE * 2 * TILE_B)

__global__ __launch_bounds__(256, 2) void gemm_mma_kernel(const __half* __restrict__ A,
                                                          const __half* __restrict__ Bt,
                                                          __half* __restrict__ C,
                                                          const float* __restrict__ Asrc,
                                                          const float* __restrict__ Adst,
                                                          float* __restrict__ sArr,
                                                          float* __restrict__ dArr,
                                                          int M, int N, int K, int Chead,
                                                          int row_off) {
    extern __shared__ __align__(16) char sm[];
    uint32_t base = smem_u32(sm);

    int tid = threadIdx.x, lane = tid & 31, wid = tid >> 5;
    int wm = (wid >> 1) * 32;
    int wn = (wid & 1) * 64;
    int brow = row_off + blockIdx.y * 128;
    int bcol = blockIdx.x * 128;

    float acc[2][8][4];
    #pragma unroll
    for (int i = 0; i < 2; i++)
        #pragma unroll
        for (int j = 0; j < 8; j++)
            #pragma unroll
            for (int q = 0; q < 4; q++) acc[i][j][q] = 0.f;

    int a_r = ((lane >> 3) & 1) * 8 + (lane & 7);
    int a_cb = (lane >> 4) * 16;
    int b_r = (lane >> 4) * 8 + (lane & 7);
    int b_cb = ((lane >> 3) & 1) * 16;

    int nch = K >> 5;

    auto loadAB = [&](int stage, int ch) {
        int k0 = ch << 5;
        uint32_t sbase = base + (uint32_t)(stage * 2 * TILE_B);
        #pragma unroll
        for (int j = 0; j < 2; j++) {
            int i = tid + j * 256;
            int seg = i & 3, row = i >> 2;
            uint32_t o = (uint32_t)(row * (PITCH * 2) + seg * 16);
            cp_async16(sbase + o, A + (size_t)(brow + row) * K + k0 + seg * 8);
            cp_async16(sbase + TILE_B + o, Bt + (size_t)(bcol + row) * K + k0 + seg * 8);
        }
    };

    #pragma unroll
    for (int s = 0; s < NSTAGE - 1; s++) {
        if (s < nch) loadAB(s, s);
        CP_COMMIT();
    }

    for (int ch = 0; ch < nch; ch++) {
        int cur = ch % NSTAGE;
        CP_WAIT(NSTAGE - 2);
        __syncthreads();
        int nl = ch + NSTAGE - 1;
        if (nl < nch) loadAB(nl % NSTAGE, nl);
        CP_COMMIT();
        uint32_t sA = base + (uint32_t)(cur * 2 * TILE_B);
        uint32_t sB = sA + TILE_B;
        #pragma unroll
        for (int ks = 0; ks < 2; ks++) {
            int kb = ks * 32;
            uint32_t ah[2][4], bh[4][4];
            #pragma unroll
            for (int mt = 0; mt < 2; mt++) {
                uint32_t ro = (uint32_t)((wm + mt * 16 + a_r) * (PITCH * 2) + kb + a_cb);
                ldm_x4(ah[mt][0], ah[mt][1], ah[mt][2], ah[mt][3], sA + ro);
            }
            #pragma unroll
            for (int nt = 0; nt < 4; nt++) {
                uint32_t ro = (uint32_t)((wn + nt * 16 + b_r) * (PITCH * 2) + kb + b_cb);
                ldm_x4(bh[nt][0], bh[nt][1], bh[nt][2], bh[nt][3], sB + ro);
            }
            #pragma unroll
            for (int nt = 0; nt < 4; nt++)
                #pragma unroll
                for (int mt = 0; mt < 2; mt++) {
                    mma_f16(acc[mt][nt * 2 + 0], ah[mt], bh[nt][0], bh[nt][1]);
                    mma_f16(acc[mt][nt * 2 + 1], ah[mt], bh[nt][2], bh[nt][3]);
                }
        }
    }

    // ---- epilogue: write fp16 C + fused attention scores ----
    int er = lane >> 2, ec = (lane & 3) * 2;
    float ps0[2] = {0.f, 0.f}, ps1[2] = {0.f, 0.f};
    float pd0[2] = {0.f, 0.f}, pd1[2] = {0.f, 0.f};
    #pragma unroll
    for (int mt = 0; mt < 2; mt++) {
        int r0 = brow + wm + mt * 16 + er;
        #pragma unroll
        for (int nt = 0; nt < 8; nt++) {
            int gc = bcol + wn + nt * 8 + ec;
            float a0 = Asrc[gc], a1 = Asrc[gc + 1];
            float b0 = Adst[gc], b1 = Adst[gc + 1];
            ps0[mt] += acc[mt][nt][0] * a0 + acc[mt][nt][1] * a1;
            pd0[mt] += acc[mt][nt][0] * b0 + acc[mt][nt][1] * b1;
            ps1[mt] += acc[mt][nt][2] * a0 + acc[mt][nt][3] * a1;
            pd1[mt] += acc[mt][nt][2] * b0 + acc[mt][nt][3] * b1;
            if (r0 < M)
                *(__half2*)&C[(size_t)r0 * N + gc] =
                    __floats2half2_rn(acc[mt][nt][0], acc[mt][nt][1]);
            if (r0 + 8 < M)
                *(__half2*)&C[(size_t)(r0 + 8) * N + gc] =
                    __floats2half2_rn(acc[mt][nt][2], acc[mt][nt][3]);
        }
    }
    #pragma unroll
    for (int o = 1; o <= 2; o <<= 1) {
        #pragma unroll
        for (int mt = 0; mt < 2; mt++) {
            ps0[mt] += __shfl_xor_sync(0xffffffffu, ps0[mt], o);
            ps1[mt] += __shfl_xor_sync(0xffffffffu, ps1[mt], o);
            pd0[mt] += __shfl_xor_sync(0xffffffffu, pd0[mt], o);
            pd1[mt] += __shfl_xor_sync(0xffffffffu, pd1[mt], o);
        }
    }
    if ((lane & 3) == 0) {
        #pragma unroll
        for (int mt = 0; mt < 2; mt++) {
            int r0 = brow + wm + mt * 16 + er;
            if (Chead == 64) {
                int Hloc = N / 64;
                int head = (bcol + wn) / 64;
                if (r0 < M)     { sArr[r0 * Hloc + head] = ps0[mt]; dArr[r0 * Hloc + head] = pd0[mt]; }
                if (r0 + 8 < M) { sArr[(r0 + 8) * Hloc + head] = ps1[mt]; dArr[(r0 + 8) * Hloc + head] = pd1[mt]; }
            } else {
                int part = (wn != 0);
                if (r0 < M)     { sArr[part * M + r0] = ps0[mt]; dArr[part * M + r0] = pd0[mt]; }
                if (r0 + 8 < M) { sArr[part * M + r0 + 8] = ps1[mt]; dArr[part * M + r0 + 8] = pd1[mt]; }
            }
        }
    }
}

// ---------------- CSR build ----------------
__device__ __forceinline__ void edge_endpoints(const int* __restrict__ ei, int e,
                                               int& src, int& dst) {
    if (e < E_RAW) { src = ei[e]; dst = ei[E_RAW + e]; }
    else           { src = dst = e - E_RAW; }
}
__global__ void csr_zero_kernel(int* __restrict__ deg, int* __restrict__ cur) {
    int i = blockIdx.x * blockDim.x + threadIdx.x;
    if (i < N_NODES) { deg[i] = 0; cur[i] = 0; }
}
__global__ void csr_count_kernel(const int* __restrict__ ei, int* __restrict__ deg) {
    int e = blockIdx.x * blockDim.x + threadIdx.x;
    if (e >= E_TOT) return;
    int dst = (e < E_RAW) ? ei[E_RAW + e] : e - E_RAW;
    atomicAdd(&deg[dst], 1);
}
__global__ void scan1_kernel(const int* __restrict__ deg, int* __restrict__ off,
                             int* __restrict__ bsum, int n) {
    __shared__ int sm[SCAN_B];
    int i = blockIdx.x * SCAN_B + threadIdx.x;
    int v = (i < n) ? deg[i] : 0;
    sm[threadIdx.x] = v;
    __syncthreads();
    for (int o = 1; o < SCAN_B; o <<= 1) {
        int t = (threadIdx.x >= o) ? sm[threadIdx.x - o] : 0;
        __syncthreads();
        sm[threadIdx.x] += t;
        __syncthreads();
    }
    if (i < n) off[i + 1] = sm[threadIdx.x];
    if (threadIdx.x == SCAN_B - 1) bsum[blockIdx.x] = sm[threadIdx.x];
}
__global__ void scan3_kernel(int* __restrict__ off, const int* __restrict__ bsum, int n) {
    __shared__ int run_s;
    int bucket = blockIdx.x >> 2;          // 256 * 4 = SCAN_B
    if (threadIdx.x == 0) {
        int run = 0;
        for (int b = 0; b < bucket; b++) run += bsum[b];
        run_s = run;
    }
    __syncthreads();
    int i = blockIdx.x * blockDim.x + threadIdx.x;
    if (i == 0) off[0] = 0;
    if (i < n) off[i + 1] += run_s;
}
__global__ void csr_scatter_kernel(const int* __restrict__ ei, const int* __restrict__ off,
                                   int* __restrict__ cur, int* __restrict__ srcs) {
    int e = blockIdx.x * blockDim.x + threadIdx.x;
    if (e >= E_TOT) return;
    int src, dst;
    edge_endpoints(ei, e, src, dst);
    int pos = atomicAdd(&cur[dst], 1);
    srcs[off[dst] + pos] = src;
}

// ---------------- fused aggregate: lane-parallel softmax, warp per dst node ----------------
template <int H, int C, bool ELU, typename OutT>
__global__ void agg_soft_kernel(const int* __restrict__ off,
                                const int* __restrict__ srcs,
                                const __half* __restrict__ xp,
                                const float* __restrict__ sArr,
                                const float* __restrict__ dArr,
                                const float* __restrict__ bias,
                                OutT* __restrict__ out,
                                int node_off, int node_cnt) {
    constexpr int HC = H * C;
    constexpr int PER = HC / 32;
    int gw = (blockIdx.x * blockDim.x + threadIdx.x) >> 5;
    int lane = threadIdx.x & 31;
    if (gw >= node_cnt) return;
    int node = node_off + gw;
    int base = lane * PER;
    int head = (H == 1) ? 0 : (lane >> 3);
    float dd;
    if (H == 1)
        dd = dArr[node] + dArr[N_NODES + node];
    else
        dd = (lane < 16) ? dArr[node * H + (lane & 3)] : 0.f;
    int s0 = off[node], s1 = off[node + 1];
    float acc[PER];
    #pragma unroll
    for (int j = 0; j < PER; j++) acc[j] = 0.f;
    float z = 0.f;

    auto accum = [&](int src, float pw) {
        if (PER == 8) {
            uint4 u = *(const uint4*)(xp + (size_t)src * HC + base);
            float2 f0 = __half22float2(*(__half2*)&u.x);
            float2 f1 = __half22float2(*(__half2*)&u.y);
            float2 f2 = __half22float2(*(__half2*)&u.z);
            float2 f3 = __half22float2(*(__half2*)&u.w);
            acc[0] = fmaf(f0.x, pw, acc[0]); acc[1] = fmaf(f0.y, pw, acc[1]);
            acc[2] = fmaf(f1.x, pw, acc[2]); acc[3] = fmaf(f1.y, pw, acc[3]);
            acc[4] = fmaf(f2.x, pw, acc[4]); acc[5] = fmaf(f2.y, pw, acc[5]);
            acc[6] = fmaf(f3.x, pw, acc[6]); acc[7] = fmaf(f3.y, pw, acc[7]);
        } else {
            uint2 u = *(const uint2*)(xp + (size_t)src * HC + base);
            float2 f0 = __half22float2(*(__half2*)&u.x);
            float2 f1 = __half22float2(*(__half2*)&u.y);
            acc[0] = fmaf(f0.x, pw, acc[0]); acc[1] = fmaf(f0.y, pw, acc[1]);
            acc[PER > 2 ? 2 : 0] = fmaf(f1.x, pw, acc[PER > 2 ? 2 : 0]);
            acc[PER > 3 ? 3 : 0] = fmaf(f1.y, pw, acc[PER > 3 ? 3 : 0]);
        }
    };

    int t = s0;
    for (; t + 3 < s1; t += 4) {
        float pa, pb, pc, pd;
        int sa, sb, sc, sd;
        if (H == 4) {
            int srcv = (lane < 16) ? srcs[t + (lane >> 2)] : 0;
            float sv = (lane < 16) ? sArr[srcv * 4 + (lane & 3)] : 0.f;
            float v = sv + dd;
            v = v > 0.f ? v : 0.2f * v;
            float p = __expf(fminf(v, 80.f));
            sa = __shfl_sync(0xffffffffu, srcv, 0);
            sb = __shfl_sync(0xffffffffu, srcv, 4);
            sc = __shfl_sync(0xffffffffu, srcv, 8);
            sd = __shfl_sync(0xffffffffu, srcv, 12);
            pa = __shfl_sync(0xffffffffu, p, head);
            pb = __shfl_sync(0xffffffffu, p, 4 + head);
            pc = __shfl_sync(0xffffffffu, p, 8 + head);
            pd = __shfl_sync(0xffffffffu, p, 12 + head);
        } else {
            int srcv = (lane < 4) ? srcs[t + lane] : 0;
            float sv = (lane < 4) ? sArr[srcv] + sArr[N_NODES + srcv] : 0.f;
            float v = sv + dd;
            v = v > 0.f ? v : 0.2f * v;
            float p = __expf(fminf(v, 80.f));
            sa = __shfl_sync(0xffffffffu, srcv, 0);
            sb = __shfl_sync(0xffffffffu, srcv, 1);
            sc = __shfl_sync(0xffffffffu, srcv, 2);
            sd = __shfl_sync(0xffffffffu, srcv, 3);
            pa = __shfl_sync(0xffffffffu, p, 0);
            pb = __shfl_sync(0xffffffffu, p, 1);
            pc = __shfl_sync(0xffffffffu, p, 2);
            pd = __shfl_sync(0xffffffffu, p, 3);
        }
        z += (pa + pb) + (pc + pd);
        accum(sa, pa);
        accum(sb, pb);
        accum(sc, pc);
        accum(sd, pd);
    }
    for (; t < s1; t++) {
        int src = srcs[t];
        float pw;
        if (H == 4) {
            float sv = (lane < 4) ? sArr[src * 4 + lane] : 0.f;
            float dv = (lane < 4) ? dd : 0.f;
            float v = sv + dv;
            v = v > 0.f ? v : 0.2f * v;
            float p = __expf(fminf(v, 80.f));
            pw = __shfl_sync(0xffffffffu, p, head);
        } else {
            float sv = (lane == 0) ? sArr[src] + sArr[N_NODES + src] : 0.f;
            float v = sv + dd;
            v = v > 0.f ? v : 0.2f * v;
            float p = __expf(fminf(v, 80.f));
            pw = __shfl_sync(0xffffffffu, p, 0);
        }
        z += pw;
        accum(src, pw);
    }

    float inv = 1.f / (z + 1e-16f);
    OutT* od = out + (size_t)node * HC + base;
    #pragma unroll
    for (int q = 0; q < PER / 4; q++) {
        float4 r;
        r.x = acc[q * 4 + 0] * inv + bias[base + q * 4 + 0];
        r.y = acc[q * 4 + 1] * inv + bias[base + q * 4 + 1];
        r.z = acc[q * 4 + 2] * inv + bias[base + q * 4 + 2];
        r.w = acc[q * 4 + 3] * inv + bias[base + q * 4 + 3];
        if (ELU) {
            r.x = r.x > 0.f ? r.x : expm1f(r.x);
            r.y = r.y > 0.f ? r.y : expm1f(r.y);
            r.z = r.z > 0.f ? r.z : expm1f(r.z);
            r.w = r.w > 0.f ? r.w : expm1f(r.w);
        }
        if (sizeof(OutT) == 2) {
            __half2* oh = (__half2*)(od + q * 4);
            oh[0] = __floats2half2_rn(r.x, r.y);
            oh[1] = __floats2half2_rn(r.z, r.w);
        } else {
            *(float4*)((float*)od + q * 4) = r;
        }
    }
}

// ---------------- host orchestration ----------------
extern "C" void kernel_launch(void* const* d_in, const int* in_sizes, int n_in,
                              void* d_out, int out_size) {
    const float* x      = (const float*)d_in[0];
    const int*   ei     = (const int*)  d_in[1];
    const float* W0     = (const float*)d_in[2];
    const float* a_src0 = (const float*)d_in[3];
    const float* a_dst0 = (const float*)d_in[4];
    const float* b0     = (const float*)d_in[5];
    const float* W1     = (const float*)d_in[6];
    const float* a_src1 = (const float*)d_in[7];
    const float* a_dst1 = (const float*)d_in[8];
    const float* b1     = (const float*)d_in[9];
    const float* W2     = (const float*)d_in[10];
    const float* a_src2 = (const float*)d_in[11];
    const float* a_dst2 = (const float*)d_in[12];
    const float* b2     = (const float*)d_in[13];

    __half *hh, *xphA, *xphB, *wh;
    float *sA, *dA, *sB, *dB;
    int *deg, *cur, *off, *bsum, *srcs;
    cudaGetSymbolAddress((void**)&hh,   g_hh);
    cudaGetSymbolAddress((void**)&xphA, g_xphA);
    cudaGetSymbolAddress((void**)&xphB, g_xphB);
    cudaGetSymbolAddress((void**)&wh,   g_wh);
    cudaGetSymbolAddress((void**)&sA,   g_sA);
    cudaGetSymbolAddress((void**)&dA,   g_dA);
    cudaGetSymbolAddress((void**)&sB,   g_sB);
    cudaGetSymbolAddress((void**)&dB,   g_dB);
    cudaGetSymbolAddress((void**)&deg,  g_deg);
    cudaGetSymbolAddress((void**)&cur,  g_cur);
    cudaGetSymbolAddress((void**)&off,  g_off);
    cudaGetSymbolAddress((void**)&bsum, g_bsum);
    cudaGetSymbolAddress((void**)&srcs, g_srcs);

    cudaFuncSetAttribute(gemm_mma_kernel, cudaFuncAttributeMaxDynamicSharedMemorySize,
                         GEMM_SMEM);

    static cudaStream_t s1 = nullptr;
    static cudaEvent_t ev[8];
    if (s1 == nullptr) {
        cudaStreamCreateWithFlags(&s1, cudaStreamNonBlocking);
        for (int i = 0; i < 8; i++) cudaEventCreateWithFlags(&ev[i], cudaEventDisableTiming);
    }

    const int GY_H0 = ROW_H0 / 128;                         // 196
    const int GY_H1 = (N_NODES - ROW_H0 + 127) / 128;       // 195
    const int AG_H0 = (ROW_H0 * 32 + 255) / 256;            // agg grid half 0
    const int AG_H1 = ((N_NODES - ROW_H0) * 32 + 255) / 256;

    auto gemm = [&](cudaStream_t st, const __half* in, const __half* w, int K, int N,
                    int Chead, const float* as, const float* ad, __half* xph,
                    float* sOut, float* dOut, int row_off, int gy) {
        dim3 grid(N / 128, gy);
        gemm_mma_kernel<<<grid, 256, GEMM_SMEM, st>>>(in, w, xph, as, ad, sOut, dOut,
                                                      N_NODES, N, K, Chead, row_off);
    };

    // ---- fork: CSR build on s1 ----
    cudaEventRecord(ev[0], 0);
    cudaStreamWaitEvent(s1, ev[0], 0);
    csr_zero_kernel<<<(N_NODES + 255) / 256, 256, 0, s1>>>(deg, cur);
    csr_count_kernel<<<(E_TOT + 255) / 256, 256, 0, s1>>>(ei, deg);
    int nblk = (N_NODES + SCAN_B - 1) / SCAN_B;
    scan1_kernel<<<nblk, SCAN_B, 0, s1>>>(deg, off, bsum, N_NODES);
    scan3_kernel<<<(N_NODES + 255) / 256, 256, 0, s1>>>(off, bsum, N_NODES);
    csr_scatter_kernel<<<(E_TOT + 255) / 256, 256, 0, s1>>>(ei, off, cur, srcs);
    cudaEventRecord(ev[1], s1);

    // main: weights + conv + gemm0 (layer0 scores/xph -> parity A)
    prep_weights_all<<<dim3(8, 8, 3), dim3(32, 8)>>>(W0, W1, W2, wh);
    conv_x_kernel<<<(N_NODES * 64 + 255) / 256, 256>>>(x, hh, N_NODES * 64);
    gemm(0, hh, wh, 128, 256, 64, a_src0, a_dst0, xphA, sA, dA, 0, GY_H0 + GY_H1);

    // join CSR before first aggregate
    cudaStreamWaitEvent(0, ev[1], 0);

    // ---- layer 0 aggregate (halves) -> hh ; layer1 gemm pipelined on s1 ----
    agg_soft_kernel<4, 64, true, __half><<<AG_H0, 256>>>(off, srcs, xphA, sA, dA, b0, hh,
                                                         0, ROW_H0);
    cudaEventRecord(ev[2], 0);
    agg_soft_kernel<4, 64, true, __half><<<AG_H1, 256>>>(off, srcs, xphA, sA, dA, b0, hh,
                                                         ROW_H0, N_NODES - ROW_H0);
    cudaEventRecord(ev[3], 0);
    cudaStreamWaitEvent(s1, ev[2], 0);
    gemm(s1, hh, wh + 65536, 256, 256, 64, a_src1, a_dst1, xphB, sB, dB, 0, GY_H0);
    cudaStreamWaitEvent(s1, ev[3], 0);
    gemm(s1, hh, wh + 65536, 256, 256, 64, a_src1, a_dst1, xphB, sB, dB, ROW_H0, GY_H1);
    cudaEventRecord(ev[4], s1);

    // ---- layer 1 aggregate (halves) -> hh ; layer2 gemm pipelined on s1 ----
    cudaStreamWaitEvent(0, ev[4], 0);
    agg_soft_kernel<4, 64, true, __half><<<AG_H0, 256>>>(off, srcs, xphB, sB, dB, b1, hh,
                                                         0, ROW_H0);
    cudaEventRecord(ev[5], 0);
    agg_soft_kernel<4, 64, true, __half><<<AG_H1, 256>>>(off, srcs, xphB, sB, dB, b1, hh,
                                                         ROW_H0, N_NODES - ROW_H0);
    cudaEventRecord(ev[6], 0);
    cudaStreamWaitEvent(s1, ev[5], 0);
    gemm(s1, hh, wh + 131072, 256, 128, 128, a_src2, a_dst2, xphA, sA, dA, 0, GY_H0);
    cudaStreamWaitEvent(s1, ev[6], 0);
    gemm(s1, hh, wh + 131072, 256, 128, 128, a_src2, a_dst2, xphA, sA, dA, ROW_H0, GY_H1);
    cudaEventRecord(ev[7], s1);

    // ---- layer 2 aggregate (full) -> d_out ----
    cudaStreamWaitEvent(0, ev[7], 0);
    agg_soft_kernel<1, 128, false, float>
        <<<(N_NODES * 32 + 255) / 256, 256>>>(off, srcs, xphA, sA, dA, b2,
                                              (float*)d_out, 0, N_NODES);
}

// round 16
// speedup vs baseline: 1.1027x; 1.1027x over previous
#include <cuda_runtime.h>
#include <cuda_fp16.h>
#include <cstdint>

#define N_NODES 50000
#define E_RAW   800000
#define E_TOT   (E_RAW + N_NODES)   // 850000 with self loops
#define MAXH    4
#define MAXHC   256
#define SCAN_B  1024

// ---------------- device scratch (static, allocation-free) ----------------
__device__ __half g_hh [(size_t)(N_NODES + 128) * MAXHC];  // fp16 features (+pad rows)
__device__ __half g_xph[(size_t)N_NODES * MAXHC];          // transformed features, fp16
__device__ __half g_wh [3 * MAXHC * MAXHC];                // W^T fp16, all 3 layers
__device__ float g_s [(size_t)N_NODES * MAXH];             // scores ([2][N] partials for layer2)
__device__ float g_d [(size_t)N_NODES * MAXH];
// CSR by destination
__device__ int g_deg [N_NODES];
__device__ int g_cur [N_NODES];
__device__ int g_off [N_NODES + 1];
__device__ int g_bsum[64];
__device__ int g_srcs[E_TOT];

// ---------------- small PTX helpers ----------------
__device__ __forceinline__ uint32_t smem_u32(const void* p) {
    uint32_t a;
    asm("{ .reg .u64 t; cvta.to.shared.u64 t, %1; cvt.u32.u64 %0, t; }" : "=r"(a) : "l"(p));
    return a;
}
__device__ __forceinline__ void ldm_x4(uint32_t& r0, uint32_t& r1, uint32_t& r2, uint32_t& r3,
                                       uint32_t addr) {
    asm volatile("ldmatrix.sync.aligned.m8n8.x4.shared.b16 {%0,%1,%2,%3}, [%4];"
                 : "=r"(r0), "=r"(r1), "=r"(r2), "=r"(r3) : "r"(addr));
}
__device__ __forceinline__ void mma_f16(float* d, const uint32_t* a, uint32_t b0, uint32_t b1) {
    asm volatile(
        "mma.sync.aligned.m16n8k16.row.col.f32.f16.f16.f32 "
        "{%0,%1,%2,%3}, {%4,%5,%6,%7}, {%8,%9}, {%0,%1,%2,%3};"
        : "+f"(d[0]), "+f"(d[1]), "+f"(d[2]), "+f"(d[3])
        : "r"(a[0]), "r"(a[1]), "r"(a[2]), "r"(a[3]), "r"(b0), "r"(b1));
}
__device__ __forceinline__ void cp_async16(uint32_t dst, const void* src) {
    asm volatile("cp.async.ca.shared.global [%0], [%1], 16;" :: "r"(dst), "l"(src));
}
#define CP_COMMIT()  asm volatile("cp.async.commit_group;")
#define CP_WAIT(n)   asm volatile("cp.async.wait_group %0;" :: "n"(n) : "memory")

// ---------------- all-layer weight transpose + fp16 convert ----------------
__global__ void prep_weights_all(const float* __restrict__ W0, const float* __restrict__ W1,
                                 const float* __restrict__ W2, __half* __restrict__ out) {
    __shared__ float t[32][33];
    int layer = blockIdx.z;
    const float* W; int K, N; __half* dst;
    if (layer == 0)      { W = W0; K = 128; N = 256; dst = out; }
    else if (layer == 1) { W = W1; K = 256; N = 256; dst = out + 65536; }
    else                 { W = W2; K = 256; N = 128; dst = out + 131072; }
    int bn = blockIdx.x * 32, bk = blockIdx.y * 32;
    if (bn >= N || bk >= K) return;
    int x = threadIdx.x, y = threadIdx.y;
    #pragma unroll
    for (int j = 0; j < 32; j += 8) t[y + j][x] = W[(size_t)(bk + y + j) * N + bn + x];
    __syncthreads();
    #pragma unroll
    for (int j = 0; j < 32; j += 8)
        dst[(size_t)(bn + y + j) * K + bk + x] = __float2half_rn(t[x][y + j]);
}

// ---------------- x (fp32) -> fp16 ----------------
__global__ void conv_x_kernel(const float* __restrict__ x, __half* __restrict__ out, int n2) {
    int i = blockIdx.x * blockDim.x + threadIdx.x;
    if (i < n2) {
        float2 v = *(const float2*)&x[i * 2];
        *(__half2*)&out[i * 2] = __floats2half2_rn(v.x, v.y);
    }
}

// ---------------- fp16 tensor GEMM, all-cp.async, 4-stage pipeline ----------------
#define PITCH    40
#define TILE_B   (128 * PITCH * 2)
#define NSTAGE   4
#define GEMM_SMEM (NSTAGE * 2 * TILE_B)

__global__ __launch_bounds__(256, 2) void gemm_mma_kernel(const __half* __restrict__ A,
                                                          const __half* __restrict__ Bt,
                                                          __half* __restrict__ C,
                                                          const float* __restrict__ Asrc,
                                                          const float* __restrict__ Adst,
                                                          float* __restrict__ sArr,
                                                          float* __restrict__ dArr,
                                                          int M, int N, int K, int Chead) {
    extern __shared__ __align__(16) char sm[];
    uint32_t base = smem_u32(sm);

    int tid = threadIdx.x, lane = tid & 31, wid = tid >> 5;
    int wm = (wid >> 1) * 32;
    int wn = (wid & 1) * 64;
    int brow = blockIdx.y * 128;
    int bcol = blockIdx.x * 128;

    float acc[2][8][4];
    #pragma unroll
    for (int i = 0; i < 2; i++)
        #pragma unroll
        for (int j = 0; j < 8; j++)
            #pragma unroll
            for (int q = 0; q < 4; q++) acc[i][j][q] = 0.f;

    int a_r = ((lane >> 3) & 1) * 8 + (lane & 7);
    int a_cb = (lane >> 4) * 16;
    int b_r = (lane >> 4) * 8 + (lane & 7);
    int b_cb = ((lane >> 3) & 1) * 16;

    int nch = K >> 5;

    auto loadAB = [&](int stage, int ch) {
        int k0 = ch << 5;
        uint32_t sbase = base + (uint32_t)(stage * 2 * TILE_B);
        #pragma unroll
        for (int j = 0; j < 2; j++) {
            int i = tid + j * 256;
            int seg = i & 3, row = i >> 2;
            uint32_t o = (uint32_t)(row * (PITCH * 2) + seg * 16);
            cp_async16(sbase + o, A + (size_t)(brow + row) * K + k0 + seg * 8);
            cp_async16(sbase + TILE_B + o, Bt + (size_t)(bcol + row) * K + k0 + seg * 8);
        }
    };

    #pragma unroll
    for (int s = 0; s < NSTAGE - 1; s++) {
        if (s < nch) loadAB(s, s);
        CP_COMMIT();
    }

    for (int ch = 0; ch < nch; ch++) {
        int cur = ch % NSTAGE;
        CP_WAIT(NSTAGE - 2);
        __syncthreads();
        int nl = ch + NSTAGE - 1;
        if (nl < nch) loadAB(nl % NSTAGE, nl);
        CP_COMMIT();
        uint32_t sA = base + (uint32_t)(cur * 2 * TILE_B);
        uint32_t sB = sA + TILE_B;
        #pragma unroll
        for (int ks = 0; ks < 2; ks++) {
            int kb = ks * 32;
            uint32_t ah[2][4], bh[4][4];
            #pragma unroll
            for (int mt = 0; mt < 2; mt++) {
                uint32_t ro = (uint32_t)((wm + mt * 16 + a_r) * (PITCH * 2) + kb + a_cb);
                ldm_x4(ah[mt][0], ah[mt][1], ah[mt][2], ah[mt][3], sA + ro);
            }
            #pragma unroll
            for (int nt = 0; nt < 4; nt++) {
                uint32_t ro = (uint32_t)((wn + nt * 16 + b_r) * (PITCH * 2) + kb + b_cb);
                ldm_x4(bh[nt][0], bh[nt][1], bh[nt][2], bh[nt][3], sB + ro);
            }
            #pragma unroll
            for (int nt = 0; nt < 4; nt++)
                #pragma unroll
                for (int mt = 0; mt < 2; mt++) {
                    mma_f16(acc[mt][nt * 2 + 0], ah[mt], bh[nt][0], bh[nt][1]);
                    mma_f16(acc[mt][nt * 2 + 1], ah[mt], bh[nt][2], bh[nt][3]);
                }
        }
    }

    // ---- epilogue: write fp16 C + fused attention scores ----
    int er = lane >> 2, ec = (lane & 3) * 2;
    float ps0[2] = {0.f, 0.f}, ps1[2] = {0.f, 0.f};
    float pd0[2] = {0.f, 0.f}, pd1[2] = {0.f, 0.f};
    #pragma unroll
    for (int mt = 0; mt < 2; mt++) {
        int r0 = brow + wm + mt * 16 + er;
        #pragma unroll
        for (int nt = 0; nt < 8; nt++) {
            int gc = bcol + wn + nt * 8 + ec;
            float a0 = Asrc[gc], a1 = Asrc[gc + 1];
            float b0 = Adst[gc], b1 = Adst[gc + 1];
            ps0[mt] += acc[mt][nt][0] * a0 + acc[mt][nt][1] * a1;
            pd0[mt] += acc[mt][nt][0] * b0 + acc[mt][nt][1] * b1;
            ps1[mt] += acc[mt][nt][2] * a0 + acc[mt][nt][3] * a1;
            pd1[mt] += acc[mt][nt][2] * b0 + acc[mt][nt][3] * b1;
            if (r0 < M)
                *(__half2*)&C[(size_t)r0 * N + gc] =
                    __floats2half2_rn(acc[mt][nt][0], acc[mt][nt][1]);
            if (r0 + 8 < M)
                *(__half2*)&C[(size_t)(r0 + 8) * N + gc] =
                    __floats2half2_rn(acc[mt][nt][2], acc[mt][nt][3]);
        }
    }
    #pragma unroll
    for (int o = 1; o <= 2; o <<= 1) {
        #pragma unroll
        for (int mt = 0; mt < 2; mt++) {
            ps0[mt] += __shfl_xor_sync(0xffffffffu, ps0[mt], o);
            ps1[mt] += __shfl_xor_sync(0xffffffffu, ps1[mt], o);
            pd0[mt] += __shfl_xor_sync(0xffffffffu, pd0[mt], o);
            pd1[mt] += __shfl_xor_sync(0xffffffffu, pd1[mt], o);
        }
    }
    if ((lane & 3) == 0) {
        #pragma unroll
        for (int mt = 0; mt < 2; mt++) {
            int r0 = brow + wm + mt * 16 + er;
            if (Chead == 64) {
                int Hloc = N / 64;
                int head = (bcol + wn) / 64;
                if (r0 < M)     { sArr[r0 * Hloc + head] = ps0[mt]; dArr[r0 * Hloc + head] = pd0[mt]; }
                if (r0 + 8 < M) { sArr[(r0 + 8) * Hloc + head] = ps1[mt]; dArr[(r0 + 8) * Hloc + head] = pd1[mt]; }
            } else {
                int part = (wn != 0);
                if (r0 < M)     { sArr[part * M + r0] = ps0[mt]; dArr[part * M + r0] = pd0[mt]; }
                if (r0 + 8 < M) { sArr[part * M + r0 + 8] = ps1[mt]; dArr[part * M + r0 + 8] = pd1[mt]; }
            }
        }
    }
}

// ---------------- CSR build ----------------
__device__ __forceinline__ void edge_endpoints(const int* __restrict__ ei, int e,
                                               int& src, int& dst) {
    if (e < E_RAW) { src = ei[e]; dst = ei[E_RAW + e]; }
    else           { src = dst = e - E_RAW; }
}
__global__ void csr_zero_kernel(int* __restrict__ deg, int* __restrict__ cur) {
    int i = blockIdx.x * blockDim.x + threadIdx.x;
    if (i < N_NODES) { deg[i] = 0; cur[i] = 0; }
}
__global__ void csr_count_kernel(const int* __restrict__ ei, int* __restrict__ deg) {
    int e = blockIdx.x * blockDim.x + threadIdx.x;
    if (e >= E_TOT) return;
    int dst = (e < E_RAW) ? ei[E_RAW + e] : e - E_RAW;
    atomicAdd(&deg[dst], 1);
}
__global__ void scan1_kernel(const int* __restrict__ deg, int* __restrict__ off,
                             int* __restrict__ bsum, int n) {
    __shared__ int sm[SCAN_B];
    int i = blockIdx.x * SCAN_B + threadIdx.x;
    int v = (i < n) ? deg[i] : 0;
    sm[threadIdx.x] = v;
    __syncthreads();
    for (int o = 1; o < SCAN_B; o <<= 1) {
        int t = (threadIdx.x >= o) ? sm[threadIdx.x - o] : 0;
        __syncthreads();
        sm[threadIdx.x] += t;
        __syncthreads();
    }
    if (i < n) off[i + 1] = sm[threadIdx.x];
    if (threadIdx.x == SCAN_B - 1) bsum[blockIdx.x] = sm[threadIdx.x];
}
__global__ void scan3_kernel(int* __restrict__ off, const int* __restrict__ bsum, int n) {
    __shared__ int run_s;
    int bucket = blockIdx.x >> 2;          // 256 * 4 = SCAN_B
    if (threadIdx.x == 0) {
        int run = 0;
        for (int b = 0; b < bucket; b++) run += bsum[b];
        run_s = run;
    }
    __syncthreads();
    int i = blockIdx.x * blockDim.x + threadIdx.x;
    if (i == 0) off[0] = 0;
    if (i < n) off[i + 1] += run_s;
}
__global__ void csr_scatter_kernel(const int* __restrict__ ei, const int* __restrict__ off,
                                   int* __restrict__ cur, int* __restrict__ srcs) {
    int e = blockIdx.x * blockDim.x + threadIdx.x;
    if (e >= E_TOT) return;
    int src, dst;
    edge_endpoints(ei, e, src, dst);
    int pos = atomicAdd(&cur[dst], 1);
    srcs[off[dst] + pos] = src;
}

// ---------------- fused aggregate: 8-edge lane-parallel softmax, warp/node ----------------
template <int H, int C, bool ELU, typename OutT>
__global__ void agg_soft_kernel(const int* __restrict__ off,
                                const int* __restrict__ srcs,
                                const __half* __restrict__ xp,
                                const float* __restrict__ sArr,
                                const float* __restrict__ dArr,
                                const float* __restrict__ bias,
                                OutT* __restrict__ out) {
    constexpr int HC = H * C;
    constexpr int PER = HC / 32;
    int gw = (blockIdx.x * blockDim.x + threadIdx.x) >> 5;
    int lane = threadIdx.x & 31;
    if (gw >= N_NODES) return;
    int node = gw;
    int base = lane * PER;
    int head = (H == 1) ? 0 : (lane >> 3);
    // per-lane dst score: H=4 -> every lane holds head (lane&3); H=1 -> uniform
    float dd;
    if (H == 1)
        dd = dArr[node] + dArr[N_NODES + node];
    else
        dd = dArr[node * H + (lane & 3)];
    int s0 = off[node], s1 = off[node + 1];
    float acc[PER];
    #pragma unroll
    for (int j = 0; j < PER; j++) acc[j] = 0.f;
    float z = 0.f;

    auto accum = [&](int src, float pw) {
        if (PER == 8) {
            uint4 u = *(const uint4*)(xp + (size_t)src * HC + base);
            float2 f0 = __half22float2(*(__half2*)&u.x);
            float2 f1 = __half22float2(*(__half2*)&u.y);
            float2 f2 = __half22float2(*(__half2*)&u.z);
            float2 f3 = __half22float2(*(__half2*)&u.w);
            acc[0] = fmaf(f0.x, pw, acc[0]); acc[1] = fmaf(f0.y, pw, acc[1]);
            acc[2] = fmaf(f1.x, pw, acc[2]); acc[3] = fmaf(f1.y, pw, acc[3]);
            acc[4] = fmaf(f2.x, pw, acc[4]); acc[5] = fmaf(f2.y, pw, acc[5]);
            acc[6] = fmaf(f3.x, pw, acc[6]); acc[7] = fmaf(f3.y, pw, acc[7]);
        } else {
            uint2 u = *(const uint2*)(xp + (size_t)src * HC + base);
            float2 f0 = __half22float2(*(__half2*)&u.x);
            float2 f1 = __half22float2(*(__half2*)&u.y);
            acc[0] = fmaf(f0.x, pw, acc[0]); acc[1] = fmaf(f0.y, pw, acc[1]);
            acc[PER > 2 ? 2 : 0] = fmaf(f1.x, pw, acc[PER > 2 ? 2 : 0]);
            acc[PER > 3 ? 3 : 0] = fmaf(f1.y, pw, acc[PER > 3 ? 3 : 0]);
        }
    };

    int t = s0;
    // ---- 8 edges per iteration: all 32 lanes active in the score stage ----
    for (; t + 7 < s1; t += 8) {
        int srcv; float p;
        if (H == 4) {
            srcv = srcs[t + (lane >> 2)];                     // edge = lane/4
            float sv = sArr[srcv * 4 + (lane & 3)];           // head = lane%4
            float v = sv + dd;
            v = v > 0.f ? v : 0.2f * v;
            p = __expf(fminf(v, 80.f));
            #pragma unroll
            for (int e = 0; e < 8; e++) {
                int se = __shfl_sync(0xffffffffu, srcv, e * 4);
                float pe = __shfl_sync(0xffffffffu, p, e * 4 + head);
                z += pe;
                accum(se, pe);
            }
        } else {
            srcv = (lane < 8) ? srcs[t + lane] : 0;
            float sv = (lane < 8) ? sArr[srcv] + sArr[N_NODES + srcv] : 0.f;
            float v = sv + dd;
            v = v > 0.f ? v : 0.2f * v;
            p = __expf(fminf(v, 80.f));
            #pragma unroll
            for (int e = 0; e < 8; e++) {
                int se = __shfl_sync(0xffffffffu, srcv, e);
                float pe = __shfl_sync(0xffffffffu, p, e);
                z += pe;
                accum(se, pe);
            }
        }
    }
    // ---- tail: scalar ----
    for (; t < s1; t++) {
        int src = srcs[t];
        float pw;
        if (H == 4) {
            float sv = (lane < 4) ? sArr[src * 4 + lane] : 0.f;
            float dv = (lane < 4) ? dd : 0.f;     // lanes 0..3 hold heads 0..3
            float v = sv + dv;
            v = v > 0.f ? v : 0.2f * v;
            float p = __expf(fminf(v, 80.f));
            pw = __shfl_sync(0xffffffffu, p, head);
        } else {
            float sv = (lane == 0) ? sArr[src] + sArr[N_NODES + src] : 0.f;
            float v = sv + dd;
            v = v > 0.f ? v : 0.2f * v;
            float p = __expf(fminf(v, 80.f));
            pw = __shfl_sync(0xffffffffu, p, 0);
        }
        z += pw;
        accum(src, pw);
    }

    float inv = 1.f / (z + 1e-16f);
    OutT* od = out + (size_t)node * HC + base;
    #pragma unroll
    for (int q = 0; q < PER / 4; q++) {
        float4 r;
        r.x = acc[q * 4 + 0] * inv + bias[base + q * 4 + 0];
        r.y = acc[q * 4 + 1] * inv + bias[base + q * 4 + 1];
        r.z = acc[q * 4 + 2] * inv + bias[base + q * 4 + 2];
        r.w = acc[q * 4 + 3] * inv + bias[base + q * 4 + 3];
        if (ELU) {
            r.x = r.x > 0.f ? r.x : expm1f(r.x);
            r.y = r.y > 0.f ? r.y : expm1f(r.y);
            r.z = r.z > 0.f ? r.z : expm1f(r.z);
            r.w = r.w > 0.f ? r.w : expm1f(r.w);
        }
        if (sizeof(OutT) == 2) {
            __half2* oh = (__half2*)(od + q * 4);
            oh[0] = __floats2half2_rn(r.x, r.y);
            oh[1] = __floats2half2_rn(r.z, r.w);
        } else {
            *(float4*)((float*)od + q * 4) = r;
        }
    }
}

// ---------------- host orchestration ----------------
struct Bufs {
    __half *hh, *xph, *wh;
    float *s, *d;
    int *deg, *cur, *off, *bsum, *srcs;
};

static void launch_gemm(const __half* in, const __half* wh, int K, int HCl, int Chead,
                        const float* a_src, const float* a_dst, const Bufs& b) {
    dim3 grid(HCl / 128, (N_NODES + 127) / 128);
    gemm_mma_kernel<<<grid, 256, GEMM_SMEM>>>(in, wh, b.xph,
                                              a_src, a_dst, b.s, b.d,
                                              N_NODES, HCl, K, Chead);
}

extern "C" void kernel_launch(void* const* d_in, const int* in_sizes, int n_in,
                              void* d_out, int out_size) {
    const float* x      = (const float*)d_in[0];
    const int*   ei     = (const int*)  d_in[1];
    const float* W0     = (const float*)d_in[2];
    const float* a_src0 = (const float*)d_in[3];
    const float* a_dst0 = (const float*)d_in[4];
    const float* b0     = (const float*)d_in[5];
    const float* W1     = (const float*)d_in[6];
    const float* a_src1 = (const float*)d_in[7];
    const float* a_dst1 = (const float*)d_in[8];
    const float* b1     = (const float*)d_in[9];
    const float* W2     = (const float*)d_in[10];
    const float* a_src2 = (const float*)d_in[11];
    const float* a_dst2 = (const float*)d_in[12];
    const float* b2     = (const float*)d_in[13];

    Bufs b;
    cudaGetSymbolAddress((void**)&b.hh,   g_hh);
    cudaGetSymbolAddress((void**)&b.xph,  g_xph);
    cudaGetSymbolAddress((void**)&b.wh,   g_wh);
    cudaGetSymbolAddress((void**)&b.s,    g_s);
    cudaGetSymbolAddress((void**)&b.d,    g_d);
    cudaGetSymbolAddress((void**)&b.deg,  g_deg);
    cudaGetSymbolAddress((void**)&b.cur,  g_cur);
    cudaGetSymbolAddress((void**)&b.off,  g_off);
    cudaGetSymbolAddress((void**)&b.bsum, g_bsum);
    cudaGetSymbolAddress((void**)&b.srcs, g_srcs);

    cudaFuncSetAttribute(gemm_mma_kernel, cudaFuncAttributeMaxDynamicSharedMemorySize,
                         GEMM_SMEM);

    // Lazily-created side stream + fork/join events (host objects only).
    static cudaStream_t s1 = nullptr;
    static cudaEvent_t evFork = nullptr, evJoin = nullptr;
    if (s1 == nullptr) {
        cudaStreamCreateWithFlags(&s1, cudaStreamNonBlocking);
        cudaEventCreateWithFlags(&evFork, cudaEventDisableTiming);
        cudaEventCreateWithFlags(&evJoin, cudaEventDisableTiming);
    }

    const int nwarp_grid = (int)(((size_t)N_NODES * 32 + 255) / 256);

    // ---- fork: CSR build on s1, layer-0 compute chain on the main stream ----
    cudaEventRecord(evFork, 0);
    cudaStreamWaitEvent(s1, evFork, 0);

    csr_zero_kernel<<<(N_NODES + 255) / 256, 256, 0, s1>>>(b.deg, b.cur);
    csr_count_kernel<<<(E_TOT + 255) / 256, 256, 0, s1>>>(ei, b.deg);
    int nblk = (N_NODES + SCAN_B - 1) / SCAN_B;
    scan1_kernel<<<nblk, SCAN_B, 0, s1>>>(b.deg, b.off, b.bsum, N_NODES);
    scan3_kernel<<<(N_NODES + 255) / 256, 256, 0, s1>>>(b.off, b.bsum, N_NODES);
    csr_scatter_kernel<<<(E_TOT + 255) / 256, 256, 0, s1>>>(ei, b.off, b.cur, b.srcs);
    cudaEventRecord(evJoin, s1);

    // main stream: weights + conv + gemm0 (independent of CSR)
    prep_weights_all<<<dim3(8, 8, 3), dim3(32, 8)>>>(W0, W1, W2, b.wh);
    conv_x_kernel<<<(N_NODES * 64 + 255) / 256, 256>>>(x, b.hh, N_NODES * 64);
    launch_gemm(b.hh, b.wh, 128, 256, 64, a_src0, a_dst0, b);

    // ---- join before first aggregate ----
    cudaStreamWaitEvent(0, evJoin, 0);

    // layer 0 aggregate -> fp16 hh
    agg_soft_kernel<4, 64, true, __half><<<nwarp_grid, 256>>>(b.off, b.srcs, b.xph,
                                                              b.s, b.d, b0, b.hh);
    // layer 1
    launch_gemm(b.hh, b.wh + 65536, 256, 256, 64, a_src1, a_dst1, b);
    agg_soft_kernel<4, 64, true, __half><<<nwarp_grid, 256>>>(b.off, b.srcs, b.xph,
                                                              b.s, b.d, b1, b.hh);
    // layer 2 (H=1, C=128): epilogue writes [2][N] partials, no init needed
    launch_gemm(b.hh, b.wh + 131072, 256, 128, 128, a_src2, a_dst2, b);
    agg_soft_kernel<1, 128, false, float><<<nwarp_grid, 256>>>(b.off, b.srcs, b.xph,
                                                               b.s, b.d, b2, (float*)d_out);
}

// round 17
// speedup vs baseline: 1.1034x; 1.0006x over previous
#include <cuda_runtime.h>
#include <cuda_fp16.h>
#include <cstdint>

#define N_NODES 50000
#define E_RAW   800000
#define E_TOT   (E_RAW + N_NODES)   // 850000 with self loops
#define MAXH    4
#define MAXHC   256
#define SCAN_B  1024

// ---------------- device scratch (static, allocation-free) ----------------
__device__ __half g_hh [(size_t)(N_NODES + 128) * MAXHC];  // fp16 features (+pad rows)
__device__ __half g_xph[(size_t)N_NODES * MAXHC];          // transformed features, fp16
__device__ __half g_wh [3 * MAXHC * MAXHC];                // W^T fp16, all 3 layers
__device__ float g_s [(size_t)N_NODES * MAXH];             // scores ([2][N] partials for layer2)
__device__ float g_d [(size_t)N_NODES * MAXH];
// CSR by destination
__device__ int g_deg [N_NODES];
__device__ int g_cur [N_NODES];
__device__ int g_off [N_NODES + 1];
__device__ int g_bsum[64];
__device__ int g_srcs[E_TOT];

// ---------------- small PTX helpers ----------------
__device__ __forceinline__ uint32_t smem_u32(const void* p) {
    uint32_t a;
    asm("{ .reg .u64 t; cvta.to.shared.u64 t, %1; cvt.u32.u64 %0, t; }" : "=r"(a) : "l"(p));
    return a;
}
__device__ __forceinline__ void ldm_x4(uint32_t& r0, uint32_t& r1, uint32_t& r2, uint32_t& r3,
                                       uint32_t addr) {
    asm volatile("ldmatrix.sync.aligned.m8n8.x4.shared.b16 {%0,%1,%2,%3}, [%4];"
                 : "=r"(r0), "=r"(r1), "=r"(r2), "=r"(r3) : "r"(addr));
}
__device__ __forceinline__ void mma_f16(float* d, const uint32_t* a, uint32_t b0, uint32_t b1) {
    asm volatile(
        "mma.sync.aligned.m16n8k16.row.col.f32.f16.f16.f32 "
        "{%0,%1,%2,%3}, {%4,%5,%6,%7}, {%8,%9}, {%0,%1,%2,%3};"
        : "+f"(d[0]), "+f"(d[1]), "+f"(d[2]), "+f"(d[3])
        : "r"(a[0]), "r"(a[1]), "r"(a[2]), "r"(a[3]), "r"(b0), "r"(b1));
}
__device__ __forceinline__ void cp_async16(uint32_t dst, const void* src) {
    asm volatile("cp.async.ca.shared.global [%0], [%1], 16;" :: "r"(dst), "l"(src));
}
#define CP_COMMIT()  asm volatile("cp.async.commit_group;")
#define CP_WAIT(n)   asm volatile("cp.async.wait_group %0;" :: "n"(n) : "memory")

// ---------------- all-layer weight transpose + fp16 convert ----------------
__global__ void prep_weights_all(const float* __restrict__ W0, const float* __restrict__ W1,
                                 const float* __restrict__ W2, __half* __restrict__ out) {
    __shared__ float t[32][33];
    int layer = blockIdx.z;
    const float* W; int K, N; __half* dst;
    if (layer == 0)      { W = W0; K = 128; N = 256; dst = out; }
    else if (layer == 1) { W = W1; K = 256; N = 256; dst = out + 65536; }
    else                 { W = W2; K = 256; N = 128; dst = out + 131072; }
    int bn = blockIdx.x * 32, bk = blockIdx.y * 32;
    if (bn >= N || bk >= K) return;
    int x = threadIdx.x, y = threadIdx.y;
    #pragma unroll
    for (int j = 0; j < 32; j += 8) t[y + j][x] = W[(size_t)(bk + y + j) * N + bn + x];
    __syncthreads();
    #pragma unroll
    for (int j = 0; j < 32; j += 8)
        dst[(size_t)(bn + y + j) * K + bk + x] = __float2half_rn(t[x][y + j]);
}

// ---------------- x (fp32) -> fp16 ----------------
__global__ void conv_x_kernel(const float* __restrict__ x, __half* __restrict__ out, int n2) {
    int i = blockIdx.x * blockDim.x + threadIdx.x;
    if (i < n2) {
        float2 v = *(const float2*)&x[i * 2];
        *(__half2*)&out[i * 2] = __floats2half2_rn(v.x, v.y);
    }
}

// ---------------- fp16 tensor GEMM, all-cp.async, 4-stage pipeline ----------------
#define PITCH    40
#define TILE_B   (128 * PITCH * 2)
#define NSTAGE   4
#define GEMM_SMEM (NSTAGE * 2 * TILE_B)

__global__ __launch_bounds__(256, 2) void gemm_mma_kernel(const __half* __restrict__ A,
                                                          const __half* __restrict__ Bt,
                                                          __half* __restrict__ C,
                                                          const float* __restrict__ Asrc,
                                                          const float* __restrict__ Adst,
                                                          float* __restrict__ sArr,
                                                          float* __restrict__ dArr,
                                                          int M, int N, int K, int Chead) {
    extern __shared__ __align__(16) char sm[];
    uint32_t base = smem_u32(sm);

    int tid = threadIdx.x, lane = tid & 31, wid = tid >> 5;
    int wm = (wid >> 1) * 32;
    int wn = (wid & 1) * 64;
    int brow = blockIdx.y * 128;
    int bcol = blockIdx.x * 128;

    float acc[2][8][4];
    #pragma unroll
    for (int i = 0; i < 2; i++)
        #pragma unroll
        for (int j = 0; j < 8; j++)
            #pragma unroll
            for (int q = 0; q < 4; q++) acc[i][j][q] = 0.f;

    int a_r = ((lane >> 3) & 1) * 8 + (lane & 7);
    int a_cb = (lane >> 4) * 16;
    int b_r = (lane >> 4) * 8 + (lane & 7);
    int b_cb = ((lane >> 3) & 1) * 16;

    int nch = K >> 5;

    auto loadAB = [&](int stage, int ch) {
        int k0 = ch << 5;
        uint32_t sbase = base + (uint32_t)(stage * 2 * TILE_B);
        #pragma unroll
        for (int j = 0; j < 2; j++) {
            int i = tid + j * 256;
            int seg = i & 3, row = i >> 2;
            uint32_t o = (uint32_t)(row * (PITCH * 2) + seg * 16);
            cp_async16(sbase + o, A + (size_t)(brow + row) * K + k0 + seg * 8);
            cp_async16(sbase + TILE_B + o, Bt + (size_t)(bcol + row) * K + k0 + seg * 8);
        }
    };

    #pragma unroll
    for (int s = 0; s < NSTAGE - 1; s++) {
        if (s < nch) loadAB(s, s);
        CP_COMMIT();
    }

    for (int ch = 0; ch < nch; ch++) {
        int cur = ch % NSTAGE;
        CP_WAIT(NSTAGE - 2);
        __syncthreads();
        int nl = ch + NSTAGE - 1;
        if (nl < nch) loadAB(nl % NSTAGE, nl);
        CP_COMMIT();
        uint32_t sA = base + (uint32_t)(cur * 2 * TILE_B);
        uint32_t sB = sA + TILE_B;
        #pragma unroll
        for (int ks = 0; ks < 2; ks++) {
            int kb = ks * 32;
            uint32_t ah[2][4], bh[4][4];
            #pragma unroll
            for (int mt = 0; mt < 2; mt++) {
                uint32_t ro = (uint32_t)((wm + mt * 16 + a_r) * (PITCH * 2) + kb + a_cb);
                ldm_x4(ah[mt][0], ah[mt][1], ah[mt][2], ah[mt][3], sA + ro);
            }
            #pragma unroll
            for (int nt = 0; nt < 4; nt++) {
                uint32_t ro = (uint32_t)((wn + nt * 16 + b_r) * (PITCH * 2) + kb + b_cb);
                ldm_x4(bh[nt][0], bh[nt][1], bh[nt][2], bh[nt][3], sB + ro);
            }
            #pragma unroll
            for (int nt = 0; nt < 4; nt++)
                #pragma unroll
                for (int mt = 0; mt < 2; mt++) {
                    mma_f16(acc[mt][nt * 2 + 0], ah[mt], bh[nt][0], bh[nt][1]);
                    mma_f16(acc[mt][nt * 2 + 1], ah[mt], bh[nt][2], bh[nt][3]);
                }
        }
    }

    // ---- epilogue: write fp16 C + fused attention scores ----
    int er = lane >> 2, ec = (lane & 3) * 2;
    float ps0[2] = {0.f, 0.f}, ps1[2] = {0.f, 0.f};
    float pd0[2] = {0.f, 0.f}, pd1[2] = {0.f, 0.f};
    #pragma unroll
    for (int mt = 0; mt < 2; mt++) {
        int r0 = brow + wm + mt * 16 + er;
        #pragma unroll
        for (int nt = 0; nt < 8; nt++) {
            int gc = bcol + wn + nt * 8 + ec;
            float a0 = Asrc[gc], a1 = Asrc[gc + 1];
            float b0 = Adst[gc], b1 = Adst[gc + 1];
            ps0[mt] += acc[mt][nt][0] * a0 + acc[mt][nt][1] * a1;
            pd0[mt] += acc[mt][nt][0] * b0 + acc[mt][nt][1] * b1;
            ps1[mt] += acc[mt][nt][2] * a0 + acc[mt][nt][3] * a1;
            pd1[mt] += acc[mt][nt][2] * b0 + acc[mt][nt][3] * b1;
            if (r0 < M)
                *(__half2*)&C[(size_t)r0 * N + gc] =
                    __floats2half2_rn(acc[mt][nt][0], acc[mt][nt][1]);
            if (r0 + 8 < M)
                *(__half2*)&C[(size_t)(r0 + 8) * N + gc] =
                    __floats2half2_rn(acc[mt][nt][2], acc[mt][nt][3]);
        }
    }
    #pragma unroll
    for (int o = 1; o <= 2; o <<= 1) {
        #pragma unroll
        for (int mt = 0; mt < 2; mt++) {
            ps0[mt] += __shfl_xor_sync(0xffffffffu, ps0[mt], o);
            ps1[mt] += __shfl_xor_sync(0xffffffffu, ps1[mt], o);
            pd0[mt] += __shfl_xor_sync(0xffffffffu, pd0[mt], o);
            pd1[mt] += __shfl_xor_sync(0xffffffffu, pd1[mt], o);
        }
    }
    if ((lane & 3) == 0) {
        #pragma unroll
        for (int mt = 0; mt < 2; mt++) {
            int r0 = brow + wm + mt * 16 + er;
            if (Chead == 64) {
                int Hloc = N / 64;
                int head = (bcol + wn) / 64;
                if (r0 < M)     { sArr[r0 * Hloc + head] = ps0[mt]; dArr[r0 * Hloc + head] = pd0[mt]; }
                if (r0 + 8 < M) { sArr[(r0 + 8) * Hloc + head] = ps1[mt]; dArr[(r0 + 8) * Hloc + head] = pd1[mt]; }
            } else {
                int part = (wn != 0);
                if (r0 < M)     { sArr[part * M + r0] = ps0[mt]; dArr[part * M + r0] = pd0[mt]; }
                if (r0 + 8 < M) { sArr[part * M + r0 + 8] = ps1[mt]; dArr[part * M + r0 + 8] = pd1[mt]; }
            }
        }
    }
}

// ---------------- CSR build ----------------
__device__ __forceinline__ void edge_endpoints(const int* __restrict__ ei, int e,
                                               int& src, int& dst) {
    if (e < E_RAW) { src = ei[e]; dst = ei[E_RAW + e]; }
    else           { src = dst = e - E_RAW; }
}
__global__ void csr_zero_kernel(int* __restrict__ deg, int* __restrict__ cur) {
    int i = blockIdx.x * blockDim.x + threadIdx.x;
    if (i < N_NODES) { deg[i] = 0; cur[i] = 0; }
}
__global__ void csr_count_kernel(const int* __restrict__ ei, int* __restrict__ deg) {
    int e = blockIdx.x * blockDim.x + threadIdx.x;
    if (e >= E_TOT) return;
    int dst = (e < E_RAW) ? ei[E_RAW + e] : e - E_RAW;
    atomicAdd(&deg[dst], 1);
}
__global__ void scan1_kernel(const int* __restrict__ deg, int* __restrict__ off,
                             int* __restrict__ bsum, int n) {
    __shared__ int sm[SCAN_B];
    int i = blockIdx.x * SCAN_B + threadIdx.x;
    int v = (i < n) ? deg[i] : 0;
    sm[threadIdx.x] = v;
    __syncthreads();
    for (int o = 1; o < SCAN_B; o <<= 1) {
        int t = (threadIdx.x >= o) ? sm[threadIdx.x - o] : 0;
        __syncthreads();
        sm[threadIdx.x] += t;
        __syncthreads();
    }
    if (i < n) off[i + 1] = sm[threadIdx.x];
    if (threadIdx.x == SCAN_B - 1) bsum[blockIdx.x] = sm[threadIdx.x];
}
__global__ void scan3_kernel(int* __restrict__ off, const int* __restrict__ bsum, int n) {
    __shared__ int run_s;
    int bucket = blockIdx.x >> 2;          // 256 * 4 = SCAN_B
    if (threadIdx.x == 0) {
        int run = 0;
        for (int b = 0; b < bucket; b++) run += bsum[b];
        run_s = run;
    }
    __syncthreads();
    int i = blockIdx.x * blockDim.x + threadIdx.x;
    if (i == 0) off[0] = 0;
    if (i < n) off[i + 1] += run_s;
}
__global__ void csr_scatter_kernel(const int* __restrict__ ei, const int* __restrict__ off,
                                   int* __restrict__ cur, int* __restrict__ srcs) {
    int e = blockIdx.x * blockDim.x + threadIdx.x;
    if (e >= E_TOT) return;
    int src, dst;
    edge_endpoints(ei, e, src, dst);
    int pos = atomicAdd(&cur[dst], 1);
    srcs[off[dst] + pos] = src;
}

// ---------------- fused aggregate: 8/4-edge lane-parallel softmax, warp/node ----------------
template <int H, int C, bool ELU, typename OutT>
__global__ void agg_soft_kernel(const int* __restrict__ off,
                                const int* __restrict__ srcs,
                                const __half* __restrict__ xp,
                                const float* __restrict__ sArr,
                                const float* __restrict__ dArr,
                                const float* __restrict__ bias,
                                OutT* __restrict__ out) {
    constexpr int HC = H * C;
    constexpr int PER = HC / 32;
    int gw = (blockIdx.x * blockDim.x + threadIdx.x) >> 5;
    int lane = threadIdx.x & 31;
    if (gw >= N_NODES) return;
    int node = gw;
    int base = lane * PER;
    int head = (H == 1) ? 0 : (lane >> 3);
    float dd;
    if (H == 1)
        dd = dArr[node] + dArr[N_NODES + node];
    else
        dd = dArr[node * H + (lane & 3)];
    int s0 = off[node], s1 = off[node + 1];
    float acc[PER];
    #pragma unroll
    for (int j = 0; j < PER; j++) acc[j] = 0.f;
    float z = 0.f;

    auto accum = [&](int src, float pw) {
        if (PER == 8) {
            uint4 u = *(const uint4*)(xp + (size_t)src * HC + base);
            float2 f0 = __half22float2(*(__half2*)&u.x);
            float2 f1 = __half22float2(*(__half2*)&u.y);
            float2 f2 = __half22float2(*(__half2*)&u.z);
            float2 f3 = __half22float2(*(__half2*)&u.w);
            acc[0] = fmaf(f0.x, pw, acc[0]); acc[1] = fmaf(f0.y, pw, acc[1]);
            acc[2] = fmaf(f1.x, pw, acc[2]); acc[3] = fmaf(f1.y, pw, acc[3]);
            acc[4] = fmaf(f2.x, pw, acc[4]); acc[5] = fmaf(f2.y, pw, acc[5]);
            acc[6] = fmaf(f3.x, pw, acc[6]); acc[7] = fmaf(f3.y, pw, acc[7]);
        } else {
            uint2 u = *(const uint2*)(xp + (size_t)src * HC + base);
            float2 f0 = __half22float2(*(__half2*)&u.x);
            float2 f1 = __half22float2(*(__half2*)&u.y);
            acc[0] = fmaf(f0.x, pw, acc[0]); acc[1] = fmaf(f0.y, pw, acc[1]);
            acc[PER > 2 ? 2 : 0] = fmaf(f1.x, pw, acc[PER > 2 ? 2 : 0]);
            acc[PER > 3 ? 3 : 0] = fmaf(f1.y, pw, acc[PER > 3 ? 3 : 0]);
        }
    };

    int t = s0;
    // ---- 8 edges per iteration: all 32 lanes active in the score stage ----
    for (; t + 7 < s1; t += 8) {
        int srcv; float p;
        if (H == 4) {
            srcv = srcs[t + (lane >> 2)];
            float sv = sArr[srcv * 4 + (lane & 3)];
            float v = sv + dd;
            v = v > 0.f ? v : 0.2f * v;
            p = __expf(fminf(v, 80.f));
            #pragma unroll
            for (int e = 0; e < 8; e++) {
                int se = __shfl_sync(0xffffffffu, srcv, e * 4);
                float pe = __shfl_sync(0xffffffffu, p, e * 4 + head);
                z += pe;
                accum(se, pe);
            }
        } else {
            srcv = (lane < 8) ? srcs[t + lane] : 0;
            float sv = (lane < 8) ? sArr[srcv] + sArr[N_NODES + srcv] : 0.f;
            float v = sv + dd;
            v = v > 0.f ? v : 0.2f * v;
            p = __expf(fminf(v, 80.f));
            #pragma unroll
            for (int e = 0; e < 8; e++) {
                int se = __shfl_sync(0xffffffffu, srcv, e);
                float pe = __shfl_sync(0xffffffffu, p, e);
                z += pe;
                accum(se, pe);
            }
        }
    }
    // ---- mid-tail: 4 edges at once ----
    if (t + 3 < s1) {
        int srcv; float p;
        if (H == 4) {
            srcv = (lane < 16) ? srcs[t + (lane >> 2)] : 0;
            float sv = (lane < 16) ? sArr[srcv * 4 + (lane & 3)] : 0.f;
            float v = sv + dd;
            v = v > 0.f ? v : 0.2f * v;
            p = __expf(fminf(v, 80.f));
            #pragma unroll
            for (int e = 0; e < 4; e++) {
                int se = __shfl_sync(0xffffffffu, srcv, e * 4);
                float pe = __shfl_sync(0xffffffffu, p, e * 4 + head);
                z += pe;
                accum(se, pe);
            }
        } else {
            srcv = (lane < 4) ? srcs[t + lane] : 0;
            float sv = (lane < 4) ? sArr[srcv] + sArr[N_NODES + srcv] : 0.f;
            float v = sv + dd;
            v = v > 0.f ? v : 0.2f * v;
            p = __expf(fminf(v, 80.f));
            #pragma unroll
            for (int e = 0; e < 4; e++) {
                int se = __shfl_sync(0xffffffffu, srcv, e);
                float pe = __shfl_sync(0xffffffffu, p, e);
                z += pe;
                accum(se, pe);
            }
        }
        t += 4;
    }
    // ---- scalar tail (<=3 edges) ----
    for (; t < s1; t++) {
        int src = srcs[t];
        float pw;
        if (H == 4) {
            float sv = (lane < 4) ? sArr[src * 4 + lane] : 0.f;
            float dv = (lane < 4) ? dd : 0.f;
            float v = sv + dv;
            v = v > 0.f ? v : 0.2f * v;
            float p = __expf(fminf(v, 80.f));
            pw = __shfl_sync(0xffffffffu, p, head);
        } else {
            float sv = (lane == 0) ? sArr[src] + sArr[N_NODES + src] : 0.f;
            float v = sv + dd;
            v = v > 0.f ? v : 0.2f * v;
            float p = __expf(fminf(v, 80.f));
            pw = __shfl_sync(0xffffffffu, p, 0);
        }
        z += pw;
        accum(src, pw);
    }

    float inv = 1.f / (z + 1e-16f);
    OutT* od = out + (size_t)node * HC + base;
    #pragma unroll
    for (int q = 0; q < PER / 4; q++) {
        float4 r;
        r.x = acc[q * 4 + 0] * inv + bias[base + q * 4 + 0];
        r.y = acc[q * 4 + 1] * inv + bias[base + q * 4 + 1];
        r.z = acc[q * 4 + 2] * inv + bias[base + q * 4 + 2];
        r.w = acc[q * 4 + 3] * inv + bias[base + q * 4 + 3];
        if (ELU) {
            r.x = r.x > 0.f ? r.x : expm1f(r.x);
            r.y = r.y > 0.f ? r.y : expm1f(r.y);
            r.z = r.z > 0.f ? r.z : expm1f(r.z);
            r.w = r.w > 0.f ? r.w : expm1f(r.w);
        }
        if (sizeof(OutT) == 2) {
            __half2* oh = (__half2*)(od + q * 4);
            oh[0] = __floats2half2_rn(r.x, r.y);
            oh[1] = __floats2half2_rn(r.z, r.w);
        } else {
            *(float4*)((float*)od + q * 4) = r;
        }
    }
}

// ---------------- host orchestration ----------------
struct Bufs {
    __half *hh, *xph, *wh;
    float *s, *d;
    int *deg, *cur, *off, *bsum, *srcs;
};

static void launch_gemm(const __half* in, const __half* wh, int K, int HCl, int Chead,
                        const float* a_src, const float* a_dst, const Bufs& b) {
    dim3 grid(HCl / 128, (N_NODES + 127) / 128);
    gemm_mma_kernel<<<grid, 256, GEMM_SMEM>>>(in, wh, b.xph,
                                              a_src, a_dst, b.s, b.d,
                                              N_NODES, HCl, K, Chead);
}

extern "C" void kernel_launch(void* const* d_in, const int* in_sizes, int n_in,
                              void* d_out, int out_size) {
    const float* x      = (const float*)d_in[0];
    const int*   ei     = (const int*)  d_in[1];
    const float* W0     = (const float*)d_in[2];
    const float* a_src0 = (const float*)d_in[3];
    const float* a_dst0 = (const float*)d_in[4];
    const float* b0     = (const float*)d_in[5];
    const float* W1     = (const float*)d_in[6];
    const float* a_src1 = (const float*)d_in[7];
    const float* a_dst1 = (const float*)d_in[8];
    const float* b1     = (const float*)d_in[9];
    const float* W2     = (const float*)d_in[10];
    const float* a_src2 = (const float*)d_in[11];
    const float* a_dst2 = (const float*)d_in[12];
    const float* b2     = (const float*)d_in[13];

    Bufs b;
    cudaGetSymbolAddress((void**)&b.hh,   g_hh);
    cudaGetSymbolAddress((void**)&b.xph,  g_xph);
    cudaGetSymbolAddress((void**)&b.wh,   g_wh);
    cudaGetSymbolAddress((void**)&b.s,    g_s);
    cudaGetSymbolAddress((void**)&b.d,    g_d);
    cudaGetSymbolAddress((void**)&b.deg,  g_deg);
    cudaGetSymbolAddress((void**)&b.cur,  g_cur);
    cudaGetSymbolAddress((void**)&b.off,  g_off);
    cudaGetSymbolAddress((void**)&b.bsum, g_bsum);
    cudaGetSymbolAddress((void**)&b.srcs, g_srcs);

    cudaFuncSetAttribute(gemm_mma_kernel, cudaFuncAttributeMaxDynamicSharedMemorySize,
                         GEMM_SMEM);

    // Lazily-created side stream + events (host objects only).
    static cudaStream_t s1 = nullptr;
    static cudaEvent_t evFork = nullptr, evConv = nullptr, evJoin = nullptr;
    if (s1 == nullptr) {
        cudaStreamCreateWithFlags(&s1, cudaStreamNonBlocking);
        cudaEventCreateWithFlags(&evFork, cudaEventDisableTiming);
        cudaEventCreateWithFlags(&evConv, cudaEventDisableTiming);
        cudaEventCreateWithFlags(&evJoin, cudaEventDisableTiming);
    }

    const int nwarp_grid = (int)(((size_t)N_NODES * 32 + 255) / 256);

    // ---- fork: conv_x + CSR build on s1; prep_weights on main ----
    cudaEventRecord(evFork, 0);
    cudaStreamWaitEvent(s1, evFork, 0);

    conv_x_kernel<<<(N_NODES * 64 + 255) / 256, 256, 0, s1>>>(x, b.hh, N_NODES * 64);
    cudaEventRecord(evConv, s1);
    csr_zero_kernel<<<(N_NODES + 255) / 256, 256, 0, s1>>>(b.deg, b.cur);
    csr_count_kernel<<<(E_TOT + 255) / 256, 256, 0, s1>>>(ei, b.deg);
    int nblk = (N_NODES + SCAN_B - 1) / SCAN_B;
    scan1_kernel<<<nblk, SCAN_B, 0, s1>>>(b.deg, b.off, b.bsum, N_NODES);
    scan3_kernel<<<(N_NODES + 255) / 256, 256, 0, s1>>>(b.off, b.bsum, N_NODES);
    csr_scatter_kernel<<<(E_TOT + 255) / 256, 256, 0, s1>>>(ei, b.off, b.cur, b.srcs);
    cudaEventRecord(evJoin, s1);

    // main stream: weights (overlaps conv_x), then gemm0 after conv done
    prep_weights_all<<<dim3(8, 8, 3), dim3(32, 8)>>>(W0, W1, W2, b.wh);
    cudaStreamWaitEvent(0, evConv, 0);
    launch_gemm(b.hh, b.wh, 128, 256, 64, a_src0, a_dst0, b);

    // ---- join CSR before first aggregate ----
    cudaStreamWaitEvent(0, evJoin, 0);

    // layer 0 aggregate -> fp16 hh
    agg_soft_kernel<4, 64, true, __half><<<nwarp_grid, 256>>>(b.off, b.srcs, b.xph,
                                                              b.s, b.d, b0, b.hh);
    // layer 1
    launch_gemm(b.hh, b.wh + 65536, 256, 256, 64, a_src1, a_dst1, b);
    agg_soft_kernel<4, 64, true, __half><<<nwarp_grid, 256>>>(b.off, b.srcs, b.xph,
                                                              b.s, b.d, b1, b.hh);
    // layer 2 (H=1, C=128): epilogue writes [2][N] partials, no init needed
    launch_gemm(b.hh, b.wh + 131072, 256, 128, 128, a_src2, a_dst2, b);
    agg_soft_kernel<1, 128, false, float><<<nwarp_grid, 256>>>(b.off, b.srcs, b.xph,
                                                               b.s, b.d, b2, (float*)d_out);
}